// round 13
// baseline (speedup 1.0000x reference)
#include <cuda_runtime.h>
#include <cuda_fp16.h>
#include <math.h>
#include <stdint.h>

#define BSZ 8
#define SEQ 1024
#define DIM 1024
#define NH 16
#define HD 64
#define MTOT 8192
#define DCAT 1088
#define DFF 2048

// fp16 intermediates (__device__ globals per allocation-free rule), half2 words
__device__ __half2 g_xh[(size_t)MTOT * 512];      // x            [m, 512w]
__device__ __half2 g_qkvh[(size_t)MTOT * 1536];   // q | k | v    [m, 1536w]
__device__ __half2 g_cath[(size_t)MTOT * 544];    // attn|inproj  [m, 544w]
__device__ __half2 g_hh[(size_t)MTOT * 1024];     // ffn hidden   [m, 1024w]

// Pre-converted weights: word(kp, n) = half2(W[2kp][n], W[2kp+1][n])
__device__ __half2 g_whq[512 * 1024];
__device__ __half2 g_whk[512 * 1024];
__device__ __half2 g_whv[512 * 1024];
__device__ __half2 g_whi[512 * 64];
__device__ __half2 g_wh1[544 * 2048];
__device__ __half2 g_wh2[1024 * 1024];

__device__ __forceinline__ unsigned h2u(__half2 h) { return *(unsigned*)&h; }
__device__ __forceinline__ __half2 u2h(unsigned u) { return *(__half2*)&u; }
__device__ __forceinline__ void mma_f16(float c[4], const unsigned a[4],
                                        unsigned b0, unsigned b1) {
    asm volatile(
        "mma.sync.aligned.m16n8k16.row.col.f32.f16.f16.f32 "
        "{%0,%1,%2,%3}, {%4,%5,%6,%7}, {%8,%9}, {%0,%1,%2,%3};"
        : "+f"(c[0]), "+f"(c[1]), "+f"(c[2]), "+f"(c[3])
        : "r"(a[0]), "r"(a[1]), "r"(a[2]), "r"(a[3]), "r"(b0), "r"(b1));
}
__device__ __forceinline__ void ldsm4(unsigned a[4], uint32_t addr) {
    asm volatile("ldmatrix.sync.aligned.m8n8.x4.shared.b16 {%0,%1,%2,%3}, [%4];"
        : "=r"(a[0]), "=r"(a[1]), "=r"(a[2]), "=r"(a[3]) : "r"(addr));
}
__device__ __forceinline__ uint32_t smem_u32(const void* p) {
    uint32_t a;
    asm("{ .reg .u64 t; cvta.to.shared.u64 t, %1; cvt.u32.u64 %0, t; }" : "=r"(a) : "l"(p));
    return a;
}
__device__ __forceinline__ void cp_async16(uint32_t dst, const void* src) {
    asm volatile("cp.async.cg.shared.global [%0], [%1], 16;" :: "r"(dst), "l"(src));
}
#define CP_COMMIT() asm volatile("cp.async.commit_group;" ::: "memory")
#define CP_WAIT0()  asm volatile("cp.async.wait_group 0;" ::: "memory")
#define CP_WAIT1()  asm volatile("cp.async.wait_group 1;" ::: "memory")

// ---------------------------------------------------------------------------
// Merged conversion kernel (one launch).
// ---------------------------------------------------------------------------
#define TX   (MTOT * 256)
#define TWQ  (512 * 256)
#define TWI  (512 * 16)
#define TW1  (544 * 512)
#define TW2  (1024 * 256)
#define TTOT (TX + 3 * TWQ + TWI + TW1 + TW2)

__device__ __forceinline__ void conv_w_task(
    const float* __restrict__ W, __half2* __restrict__ Wh, int N, int t)
{
    int nq = N >> 2;
    int kp = t / nq, n4 = (t - kp * nq) << 2;
    float4 a = *(const float4*)(W + (size_t)(2 * kp) * N + n4);
    float4 b = *(const float4*)(W + (size_t)(2 * kp + 1) * N + n4);
    uint4 o;
    o.x = h2u(__floats2half2_rn(a.x, b.x));
    o.y = h2u(__floats2half2_rn(a.y, b.y));
    o.z = h2u(__floats2half2_rn(a.z, b.z));
    o.w = h2u(__floats2half2_rn(a.w, b.w));
    *(uint4*)(Wh + (size_t)kp * N + n4) = o;
}

__global__ __launch_bounds__(256) void conv_all(
    const float* __restrict__ x,
    const float* __restrict__ Wq, const float* __restrict__ Wk,
    const float* __restrict__ Wv, const float* __restrict__ Wi,
    const float* __restrict__ W1, const float* __restrict__ W2)
{
    int idx = blockIdx.x * 256 + threadIdx.x;
    if (idx < TX) {
        int row = idx >> 8, c4 = (idx & 255) << 2;
        float4 v = *(const float4*)(x + (size_t)row * DIM + c4);
        uint2 o;
        o.x = h2u(__floats2half2_rn(v.x, v.y));
        o.y = h2u(__floats2half2_rn(v.z, v.w));
        *(uint2*)((unsigned*)g_xh + (size_t)row * 512 + (c4 >> 1)) = o;
        return;
    }
    idx -= TX;
    if (idx < TWQ) { conv_w_task(Wq, g_whq, 1024, idx); return; }
    idx -= TWQ;
    if (idx < TWQ) { conv_w_task(Wk, g_whk, 1024, idx); return; }
    idx -= TWQ;
    if (idx < TWQ) { conv_w_task(Wv, g_whv, 1024, idx); return; }
    idx -= TWQ;
    if (idx < TWI) { conv_w_task(Wi, g_whi, 64, idx); return; }
    idx -= TWI;
    if (idx < TW1) { conv_w_task(W1, g_wh1, 2048, idx); return; }
    idx -= TW1;
    if (idx < TW2) { conv_w_task(W2, g_wh2, 1024, idx); return; }
}

// ---------------------------------------------------------------------------
// fp16 GEMM v8: CTA 128x128, BK=64, 8 warps (2M x 4N), 3-stage cp.async
// pipeline (loads run 2 chunks ahead), ldmatrix A frags, 2 CTAs/SM.
// ---------------------------------------------------------------------------
#define ASTR5 36
#define BSTR5 136
#define A5W (128 * ASTR5)     // 4608
#define B5W (32 * BSTR5)      // 4352
#define STG5 (A5W + B5W)      // 8960 words
#define SMEM8 (3 * STG5 * 4)  // 107520 B

template<bool OUTH, bool RELU>
__device__ __forceinline__ void gemm_core8(
    const __half2* __restrict__ Ah, int ldaw, int K, int m0,
    const __half2* __restrict__ Bh, int ldw, int n0w, int ncols,
    const float* __restrict__ bias, void* Cp, int ldCo, int c0o,
    unsigned* smw)
{
    const int tid = threadIdx.x, lane = tid & 31, warp = tid >> 5;
    const int wm = warp & 1, wn = warp >> 1;
    const int g = lane >> 2, tg = lane & 3;
    const uint32_t ss = smem_u32(smw);

    // ldmatrix m8n8.x4 per-lane source row (matrices m0k0,m8k0,m0k8,m8k8)
    const int lrow = lane & 7, sel = lane >> 3;
    const int arow_l = wm * 64 + ((sel & 1) << 3) + lrow;
    const int akoff_l = (sel >> 1) << 2;

    float acc[4][4][4];
#pragma unroll
    for (int mi = 0; mi < 4; mi++)
#pragma unroll
        for (int ni = 0; ni < 4; ni++)
#pragma unroll
            for (int r = 0; r < 4; r++) acc[mi][ni][r] = 0.f;

    const int NC = K >> 6;
    const int gpr = ncols >> 2;
    const int ngr = 32 * gpr;

    // loader lambda: chunk ch into stage st
    auto load_chunk = [&](int ch, int st) {
        const int k0w = ch << 5;
        const int ao = st * STG5, bo = st * STG5 + A5W;
#pragma unroll
        for (int i = 0; i < 4; i++) {
            int gi = i * 256 + tid;
            int row = gi >> 3, c4 = (gi & 7) << 2;
            cp_async16(ss + (ao + row * ASTR5 + c4) * 4,
                       Ah + (size_t)(m0 + row) * ldaw + k0w + c4);
        }
        for (int gi = tid; gi < ngr; gi += 256) {
            int row = gi / gpr, n4 = (gi - row * gpr) << 2;
            cp_async16(ss + (bo + row * BSTR5 + n4) * 4,
                       Bh + (size_t)(k0w + row) * ldw + n0w + n4);
        }
        CP_COMMIT();
    };

    // --- prologue: chunks 0, 1 ---
    load_chunk(0, 0);
    if (NC > 1) load_chunk(1, 1);

    int s = 0;
    for (int ch = 0; ch < NC; ch++) {
        // wait for chunk ch's group (leave ch+1 in flight if it exists)
        if (ch + 1 < NC) { CP_WAIT1(); } else { CP_WAIT0(); }
        __syncthreads();   // all lanes see stage s data; stage of ch-1 free

        // prefetch chunk ch+2 into the stage just vacated by ch-1
        if (ch + 2 < NC) {
            int st2 = s + 2; if (st2 >= 3) st2 -= 3;
            load_chunk(ch + 2, st2);
        }

        const unsigned* Bw = smw + s * STG5 + A5W;
        const uint32_t abase = ss + (s * STG5 + arow_l * ASTR5 + akoff_l) * 4;
#pragma unroll
        for (int ks = 0; ks < 4; ks++) {
            unsigned a[4][4];
#pragma unroll
            for (int mi = 0; mi < 4; mi++)
                ldsm4(a[mi], abase + (mi * 16 * ASTR5 + ks * 8) * 4);
#pragma unroll
            for (int ni = 0; ni < 4; ni++) {
                const unsigned* bp = Bw + (ks * 8 + tg) * BSTR5 + wn * 32 + ni * 8 + g;
                unsigned b0 = bp[0], b1 = bp[4 * BSTR5];
#pragma unroll
                for (int mi = 0; mi < 4; mi++)
                    mma_f16(acc[mi][ni], a[mi], b0, b1);
            }
        }
        __syncthreads();   // stage s free for reuse by ch+3's loader next iter
        if (++s == 3) s = 0;
    }

    // ---- epilogue ----
    if (wn * 32 >= ncols) return;
#pragma unroll
    for (int mi = 0; mi < 4; mi++) {
        int r = m0 + wm * 64 + mi * 16 + g;
#pragma unroll
        for (int ni = 0; ni < 4; ni++) {
            int cl = wn * 32 + ni * 8 + 2 * tg;
            float b0 = bias[cl], b1 = bias[cl + 1];
            float v0 = acc[mi][ni][0] + b0, v1 = acc[mi][ni][1] + b1;
            float v2 = acc[mi][ni][2] + b0, v3 = acc[mi][ni][3] + b1;
            if (RELU) {
                v0 = fmaxf(v0, 0.f); v1 = fmaxf(v1, 0.f);
                v2 = fmaxf(v2, 0.f); v3 = fmaxf(v3, 0.f);
            }
            if (OUTH) {
                unsigned* Ch = (unsigned*)Cp;
                int w = c0o + wn * 16 + ni * 4 + tg;
                Ch[(size_t)r * ldCo + w]       = h2u(__floats2half2_rn(v0, v1));
                Ch[(size_t)(r + 8) * ldCo + w] = h2u(__floats2half2_rn(v2, v3));
            } else {
                float* Cf = (float*)Cp;
                *(float2*)(Cf + (size_t)r * ldCo + c0o + cl)       = make_float2(v0, v1);
                *(float2*)(Cf + (size_t)(r + 8) * ldCo + c0o + cl) = make_float2(v2, v3);
            }
        }
    }
}

__global__ __launch_bounds__(256, 2) void qkv_v8(
    const float* __restrict__ bq, const float* __restrict__ bk,
    const float* __restrict__ bv, const float* __restrict__ bi)
{
    extern __shared__ unsigned smw[];
    const int nt = blockIdx.x, m0 = blockIdx.y * 128;
    if (nt < 24) {
        const int seg = nt >> 3, tile = nt & 7;
        const __half2* W = (seg == 0) ? g_whq : (seg == 1) ? g_whk : g_whv;
        const float* bb  = (seg == 0) ? bq : (seg == 1) ? bk : bv;
        gemm_core8<true, false>(g_xh, 512, 1024, m0, W, 1024, tile * 128, 128,
                                bb + tile * 128, g_qkvh, 1536,
                                seg * 512 + tile * 64, smw);
    } else {
        gemm_core8<true, false>(g_xh, 512, 1024, m0, g_whi, 64, 0, 64,
                                bi, g_cath, 544, 512, smw);
    }
}

__global__ __launch_bounds__(256, 2) void ffn1_v8(const float* __restrict__ b1)
{
    extern __shared__ unsigned smw[];
    const int n0 = blockIdx.x * 128;
    gemm_core8<true, true>(g_cath, 544, 1088, blockIdx.y * 128, g_wh1, DFF, n0, 128,
                           b1 + n0, g_hh, 1024, n0 >> 1, smw);
}

__global__ __launch_bounds__(256, 2) void ffn2_v8(const float* __restrict__ b2,
                                                  float* __restrict__ out)
{
    extern __shared__ unsigned smw[];
    const int n0 = blockIdx.x * 128;
    gemm_core8<false, false>(g_hh, 1024, 2048, blockIdx.y * 128, g_wh2, DIM, n0, 128,
                             b2 + n0, out, DIM, n0, smw);
}

// ---------------------------------------------------------------------------
// fp16 flash attention: 256 thr / 8 warps, 128 q rows, 32-key chunks,
// Q fragments hoisted to registers.
// ---------------------------------------------------------------------------
#define AQSTR 36
#define AVSTR 20
#define APSTR 20

__global__ __launch_bounds__(256) void attn_f16()
{
    __shared__ unsigned Qs[128 * AQSTR];
    __shared__ unsigned Ks[32 * AQSTR];
    __shared__ unsigned Vt[64 * AVSTR];
    __shared__ unsigned Ps[8 * 16 * APSTR];

    const int tid = threadIdx.x, lane = tid & 31, warp = tid >> 5;
    const int g = lane >> 2, tg = lane & 3;
    const int b = blockIdx.z, h = blockIdx.y, q0 = blockIdx.x * 128;

    const unsigned* qbase = (const unsigned*)g_qkvh + (size_t)(b * SEQ) * 1536 + h * 32;
    const unsigned* kbase = qbase + 512;
    const unsigned* vbase = qbase + 1024;

    // Q tile 128 rows x 32 words, scaled by 0.125
    {
        const __half2 qsc = __float2half2_rn(0.125f);
#pragma unroll
        for (int i = 0; i < 4; i++) {
            int idx = i * 256 + tid;
            int row = idx >> 3, c4 = (idx & 7) << 2;
            uint4 v = *(const uint4*)(qbase + (size_t)(q0 + row) * 1536 + c4);
            __half2* hp = (__half2*)&v;
            hp[0] = __hmul2(hp[0], qsc); hp[1] = __hmul2(hp[1], qsc);
            hp[2] = __hmul2(hp[2], qsc); hp[3] = __hmul2(hp[3], qsc);
            *(uint4*)(Qs + row * AQSTR + c4) = v;
        }
    }
    __syncthreads();

    // Hoist Q fragments into registers (loop-invariant)
    unsigned aq[4][4];
#pragma unroll
    for (int ks = 0; ks < 4; ks++) {
        const unsigned* qp = Qs + (warp * 16 + g) * AQSTR + ks * 8 + tg;
        aq[ks][0] = qp[0];             aq[ks][2] = qp[4];
        aq[ks][1] = qp[8 * AQSTR];     aq[ks][3] = qp[8 * AQSTR + 4];
    }

    float rowm[2] = {-1e30f, -1e30f};
    float rowl[2] = {0.f, 0.f};
    float o[8][4];
#pragma unroll
    for (int nf = 0; nf < 8; nf++)
#pragma unroll
        for (int r = 0; r < 4; r++) o[nf][r] = 0.f;

    const int qrow0 = q0 + warp * 16 + g;
    unsigned* Pw = Ps + warp * 16 * APSTR;

    for (int c0 = 0; c0 < SEQ; c0 += 32) {
        __syncthreads();
        // K tile 32 rows x 32 words
        {
            int row = tid >> 3, c4 = (tid & 7) << 2;
            *(uint4*)(Ks + row * AQSTR + c4) =
                *(const uint4*)(kbase + (size_t)(c0 + row) * 1536 + c4);
        }
        // V transpose to Vt[d][kp]
        {
            int wi = tid & 31, rb = tid >> 5;
#pragma unroll
            for (int rr = rb; rr < 16; rr += 8) {
                unsigned u0 = vbase[(size_t)(c0 + 2 * rr) * 1536 + wi];
                unsigned u1 = vbase[(size_t)(c0 + 2 * rr + 1) * 1536 + wi];
                __half2 va = u2h(u0), vb = u2h(u1);
                Vt[(2 * wi) * AVSTR + rr]     = h2u(__lows2half2(va, vb));
                Vt[(2 * wi + 1) * AVSTR + rr] = h2u(__highs2half2(va, vb));
            }
        }
        __syncthreads();

        // S = Q · K^T
        float s[4][4];
#pragma unroll
        for (int ni = 0; ni < 4; ni++)
#pragma unroll
            for (int r = 0; r < 4; r++) s[ni][r] = 0.f;
#pragma unroll
        for (int ks = 0; ks < 4; ks++) {
#pragma unroll
            for (int ni = 0; ni < 4; ni++) {
                const unsigned* kp = Ks + (ni * 8 + g) * AQSTR + ks * 8 + tg;
                mma_f16(s[ni], aq[ks], kp[0], kp[4]);
            }
        }

        // Diagonal mask + online softmax
        float cm0 = -1e30f, cm1 = -1e30f;
#pragma unroll
        for (int ni = 0; ni < 4; ni++) {
            int col = c0 + ni * 8 + 2 * tg;
            if (col     == qrow0)     s[ni][0] = -1e30f;
            if (col + 1 == qrow0)     s[ni][1] = -1e30f;
            if (col     == qrow0 + 8) s[ni][2] = -1e30f;
            if (col + 1 == qrow0 + 8) s[ni][3] = -1e30f;
            cm0 = fmaxf(cm0, fmaxf(s[ni][0], s[ni][1]));
            cm1 = fmaxf(cm1, fmaxf(s[ni][2], s[ni][3]));
        }
        cm0 = fmaxf(cm0, __shfl_xor_sync(0xffffffffu, cm0, 1));
        cm0 = fmaxf(cm0, __shfl_xor_sync(0xffffffffu, cm0, 2));
        cm1 = fmaxf(cm1, __shfl_xor_sync(0xffffffffu, cm1, 1));
        cm1 = fmaxf(cm1, __shfl_xor_sync(0xffffffffu, cm1, 2));

        float mn0 = fmaxf(rowm[0], cm0), mn1 = fmaxf(rowm[1], cm1);
        float sc0 = __expf(rowm[0] - mn0), sc1 = __expf(rowm[1] - mn1);
        rowm[0] = mn0; rowm[1] = mn1;
        rowl[0] *= sc0; rowl[1] *= sc1;
#pragma unroll
        for (int nf = 0; nf < 8; nf++) {
            o[nf][0] *= sc0; o[nf][1] *= sc0;
            o[nf][2] *= sc1; o[nf][3] *= sc1;
        }

        float ls0 = 0.f, ls1 = 0.f;
#pragma unroll
        for (int ni = 0; ni < 4; ni++) {
            float p0 = __expf(s[ni][0] - mn0), p1 = __expf(s[ni][1] - mn0);
            float p2 = __expf(s[ni][2] - mn1), p3 = __expf(s[ni][3] - mn1);
            ls0 += p0 + p1; ls1 += p2 + p3;
            Pw[g * APSTR + ni * 4 + tg]       = h2u(__floats2half2_rn(p0, p1));
            Pw[(g + 8) * APSTR + ni * 4 + tg] = h2u(__floats2half2_rn(p2, p3));
        }
        ls0 += __shfl_xor_sync(0xffffffffu, ls0, 1);
        ls0 += __shfl_xor_sync(0xffffffffu, ls0, 2);
        ls1 += __shfl_xor_sync(0xffffffffu, ls1, 1);
        ls1 += __shfl_xor_sync(0xffffffffu, ls1, 2);
        rowl[0] += ls0; rowl[1] += ls1;
        __syncwarp();

        // O += P · V
#pragma unroll
        for (int ks = 0; ks < 2; ks++) {
            unsigned a[4];
            a[0] = Pw[g * APSTR + ks * 8 + tg];
            a[1] = Pw[(g + 8) * APSTR + ks * 8 + tg];
            a[2] = Pw[g * APSTR + ks * 8 + tg + 4];
            a[3] = Pw[(g + 8) * APSTR + ks * 8 + tg + 4];
#pragma unroll
            for (int nf = 0; nf < 8; nf++) {
                const unsigned* vp = Vt + (nf * 8 + g) * AVSTR + ks * 8 + tg;
                mma_f16(o[nf], a, vp[0], vp[4]);
            }
        }
    }

    // Epilogue
    float inv0 = 1.f / rowl[0], inv1 = 1.f / rowl[1];
    unsigned* orow = (unsigned*)g_cath + (size_t)(b * SEQ + qrow0) * 544 + h * 32;
#pragma unroll
    for (int nf = 0; nf < 8; nf++) {
        int w = nf * 4 + tg;
        orow[w]           = h2u(__floats2half2_rn(o[nf][0] * inv0, o[nf][1] * inv0));
        orow[8 * 544 + w] = h2u(__floats2half2_rn(o[nf][2] * inv1, o[nf][3] * inv1));
    }
}

// ---------------------------------------------------------------------------
extern "C" void kernel_launch(void* const* d_in, const int* in_sizes, int n_in,
                              void* d_out, int out_size)
{
    const float* x   = (const float*)d_in[0];
    const float* Wq  = (const float*)d_in[1];
    const float* bq  = (const float*)d_in[2];
    const float* Wk  = (const float*)d_in[3];
    const float* bk  = (const float*)d_in[4];
    const float* Wv  = (const float*)d_in[5];
    const float* bv  = (const float*)d_in[6];
    const float* Wi  = (const float*)d_in[7];
    const float* bi  = (const float*)d_in[8];
    const float* W1  = (const float*)d_in[9];
    const float* b1  = (const float*)d_in[10];
    const float* W2  = (const float*)d_in[11];
    const float* b2  = (const float*)d_in[12];
    float* out = (float*)d_out;

    static bool configured = false;
    if (!configured) {
        cudaFuncSetAttribute(qkv_v8,  cudaFuncAttributeMaxDynamicSharedMemorySize, SMEM8);
        cudaFuncSetAttribute(ffn1_v8, cudaFuncAttributeMaxDynamicSharedMemorySize, SMEM8);
        cudaFuncSetAttribute(ffn2_v8, cudaFuncAttributeMaxDynamicSharedMemorySize, SMEM8);
        configured = true;
    }

    // 1: all conversions
    conv_all<<<(TTOT + 255) / 256, 256>>>(x, Wq, Wk, Wv, Wi, W1, W2);
    // 2: QKV + input projection
    qkv_v8<<<dim3(25, 64), 256, SMEM8>>>(bq, bk, bv, bi);
    // 3: Attention -> g_cath[:, 0:512w]
    attn_f16<<<dim3(SEQ / 128, NH, BSZ), 256>>>();
    // 4: FFN1 -> g_hh (relu)
    ffn1_v8<<<dim3(DFF / 128, MTOT / 128), 256, SMEM8>>>(b1);
    // 5: FFN2 -> out (fp32)   [ncu capture target]
    ffn2_v8<<<dim3(DIM / 128, MTOT / 128), 256, SMEM8>>>(b2, out);
}

// round 14
// speedup vs baseline: 1.4564x; 1.4564x over previous
#include <cuda_runtime.h>
#include <cuda_fp16.h>
#include <math.h>
#include <stdint.h>

#define BSZ 8
#define SEQ 1024
#define DIM 1024
#define NH 16
#define HD 64
#define MTOT 8192
#define DCAT 1088
#define DFF 2048

// fp16 intermediates (__device__ globals per allocation-free rule), half2 words
__device__ __half2 g_xh[(size_t)MTOT * 512];      // x            [m, 512w]
__device__ __half2 g_qkvh[(size_t)MTOT * 1536];   // q | k | v    [m, 1536w]
__device__ __half2 g_cath[(size_t)MTOT * 544];    // attn|inproj  [m, 544w]
__device__ __half2 g_hh[(size_t)MTOT * 1024];     // ffn hidden   [m, 1024w]

// Pre-converted weights: word(kp, n) = half2(W[2kp][n], W[2kp+1][n])
__device__ __half2 g_whq[512 * 1024];
__device__ __half2 g_whk[512 * 1024];
__device__ __half2 g_whv[512 * 1024];
__device__ __half2 g_whi[512 * 64];
__device__ __half2 g_wh1[544 * 2048];
__device__ __half2 g_wh2[1024 * 1024];

__device__ __forceinline__ unsigned h2u(__half2 h) { return *(unsigned*)&h; }
__device__ __forceinline__ __half2 u2h(unsigned u) { return *(__half2*)&u; }
__device__ __forceinline__ void mma_f16(float c[4], const unsigned a[4],
                                        unsigned b0, unsigned b1) {
    asm volatile(
        "mma.sync.aligned.m16n8k16.row.col.f32.f16.f16.f32 "
        "{%0,%1,%2,%3}, {%4,%5,%6,%7}, {%8,%9}, {%0,%1,%2,%3};"
        : "+f"(c[0]), "+f"(c[1]), "+f"(c[2]), "+f"(c[3])
        : "r"(a[0]), "r"(a[1]), "r"(a[2]), "r"(a[3]), "r"(b0), "r"(b1));
}
__device__ __forceinline__ void ldsm4(unsigned a[4], uint32_t addr) {
    asm volatile("ldmatrix.sync.aligned.m8n8.x4.shared.b16 {%0,%1,%2,%3}, [%4];"
        : "=r"(a[0]), "=r"(a[1]), "=r"(a[2]), "=r"(a[3]) : "r"(addr));
}
__device__ __forceinline__ uint32_t smem_u32(const void* p) {
    uint32_t a;
    asm("{ .reg .u64 t; cvta.to.shared.u64 t, %1; cvt.u32.u64 %0, t; }" : "=r"(a) : "l"(p));
    return a;
}
__device__ __forceinline__ void cp_async16(uint32_t dst, const void* src) {
    asm volatile("cp.async.cg.shared.global [%0], [%1], 16;" :: "r"(dst), "l"(src));
}
#define CP_COMMIT() asm volatile("cp.async.commit_group;" ::: "memory")
#define CP_WAIT0()  asm volatile("cp.async.wait_group 0;" ::: "memory")

// ---------------------------------------------------------------------------
// Merged conversion kernel (one launch).
// ---------------------------------------------------------------------------
#define TX   (MTOT * 256)
#define TWQ  (512 * 256)
#define TWI  (512 * 16)
#define TW1  (544 * 512)
#define TW2  (1024 * 256)
#define TTOT (TX + 3 * TWQ + TWI + TW1 + TW2)

__device__ __forceinline__ void conv_w_task(
    const float* __restrict__ W, __half2* __restrict__ Wh, int N, int t)
{
    int nq = N >> 2;
    int kp = t / nq, n4 = (t - kp * nq) << 2;
    float4 a = *(const float4*)(W + (size_t)(2 * kp) * N + n4);
    float4 b = *(const float4*)(W + (size_t)(2 * kp + 1) * N + n4);
    uint4 o;
    o.x = h2u(__floats2half2_rn(a.x, b.x));
    o.y = h2u(__floats2half2_rn(a.y, b.y));
    o.z = h2u(__floats2half2_rn(a.z, b.z));
    o.w = h2u(__floats2half2_rn(a.w, b.w));
    *(uint4*)(Wh + (size_t)kp * N + n4) = o;
}

__global__ __launch_bounds__(256) void conv_all(
    const float* __restrict__ x,
    const float* __restrict__ Wq, const float* __restrict__ Wk,
    const float* __restrict__ Wv, const float* __restrict__ Wi,
    const float* __restrict__ W1, const float* __restrict__ W2)
{
    int idx = blockIdx.x * 256 + threadIdx.x;
    if (idx < TX) {
        int row = idx >> 8, c4 = (idx & 255) << 2;
        float4 v = *(const float4*)(x + (size_t)row * DIM + c4);
        uint2 o;
        o.x = h2u(__floats2half2_rn(v.x, v.y));
        o.y = h2u(__floats2half2_rn(v.z, v.w));
        *(uint2*)((unsigned*)g_xh + (size_t)row * 512 + (c4 >> 1)) = o;
        return;
    }
    idx -= TX;
    if (idx < TWQ) { conv_w_task(Wq, g_whq, 1024, idx); return; }
    idx -= TWQ;
    if (idx < TWQ) { conv_w_task(Wk, g_whk, 1024, idx); return; }
    idx -= TWQ;
    if (idx < TWQ) { conv_w_task(Wv, g_whv, 1024, idx); return; }
    idx -= TWQ;
    if (idx < TWI) { conv_w_task(Wi, g_whi, 64, idx); return; }
    idx -= TWI;
    if (idx < TW1) { conv_w_task(W1, g_wh1, 2048, idx); return; }
    idx -= TW1;
    if (idx < TW2) { conv_w_task(W2, g_wh2, 1024, idx); return; }
}

// ---------------------------------------------------------------------------
// fp16 GEMM v6 (proven 611us shape): BK=64, ldmatrix A fragments.
// CTA 128x128, 8 warps (2M x 4N), 2-stage double buffer, 2 CTAs/SM.
// ---------------------------------------------------------------------------
#define ASTR5 36
#define BSTR5 136
#define A5W (128 * ASTR5)     // 4608
#define B5W (32 * BSTR5)      // 4352
#define STG5 (A5W + B5W)      // 8960 words
#define SMEM5 (2 * STG5 * 4)  // 71680 B

template<bool OUTH, bool RELU>
__device__ __forceinline__ void gemm_core6(
    const __half2* __restrict__ Ah, int ldaw, int K, int m0,
    const __half2* __restrict__ Bh, int ldw, int n0w, int ncols,
    const float* __restrict__ bias, void* Cp, int ldCo, int c0o,
    unsigned* smw)
{
    const int tid = threadIdx.x, lane = tid & 31, warp = tid >> 5;
    const int wm = warp & 1, wn = warp >> 1;
    const int g = lane >> 2, tg = lane & 3;
    const uint32_t ss = smem_u32(smw);

    // ldmatrix m8n8.x4 per-lane source row (matrices m0k0,m8k0,m0k8,m8k8)
    const int lrow = lane & 7, sel = lane >> 3;
    const int arow_l = wm * 64 + ((sel & 1) << 3) + lrow;
    const int akoff_l = (sel >> 1) << 2;

    const int aoff[2] = {0, STG5};
    const int boff[2] = {A5W, STG5 + A5W};

    float acc[4][4][4];
#pragma unroll
    for (int mi = 0; mi < 4; mi++)
#pragma unroll
        for (int ni = 0; ni < 4; ni++)
#pragma unroll
            for (int r = 0; r < 4; r++) acc[mi][ni][r] = 0.f;

    const int NC = K >> 6;
    const int gpr = ncols >> 2;
    const int ngr = 32 * gpr;

    // --- prologue: chunk 0 ---
#pragma unroll
    for (int i = 0; i < 4; i++) {
        int gi = i * 256 + tid;
        int row = gi >> 3, c4 = (gi & 7) << 2;
        cp_async16(ss + (aoff[0] + row * ASTR5 + c4) * 4,
                   Ah + (size_t)(m0 + row) * ldaw + c4);
    }
    for (int gi = tid; gi < ngr; gi += 256) {
        int row = gi / gpr, n4 = (gi - row * gpr) << 2;
        cp_async16(ss + (boff[0] + row * BSTR5 + n4) * 4,
                   Bh + (size_t)row * ldw + n0w + n4);
    }
    CP_COMMIT();
    CP_WAIT0();
    __syncthreads();

    for (int ch = 0; ch < NC; ch++) {
        const int s = ch & 1;
        const bool more = (ch + 1 < NC);
        if (more) {
            const int k0w = (ch + 1) << 5;
#pragma unroll
            for (int i = 0; i < 4; i++) {
                int gi = i * 256 + tid;
                int row = gi >> 3, c4 = (gi & 7) << 2;
                cp_async16(ss + (aoff[s ^ 1] + row * ASTR5 + c4) * 4,
                           Ah + (size_t)(m0 + row) * ldaw + k0w + c4);
            }
            for (int gi = tid; gi < ngr; gi += 256) {
                int row = gi / gpr, n4 = (gi - row * gpr) << 2;
                cp_async16(ss + (boff[s ^ 1] + row * BSTR5 + n4) * 4,
                           Bh + (size_t)(k0w + row) * ldw + n0w + n4);
            }
            CP_COMMIT();
        }

        const unsigned* Bw = smw + boff[s];
        const uint32_t abase = ss + (aoff[s] + arow_l * ASTR5 + akoff_l) * 4;
#pragma unroll
        for (int ks = 0; ks < 4; ks++) {
            unsigned a[4][4];
#pragma unroll
            for (int mi = 0; mi < 4; mi++)
                ldsm4(a[mi], abase + (mi * 16 * ASTR5 + ks * 8) * 4);
#pragma unroll
            for (int ni = 0; ni < 4; ni++) {
                const unsigned* bp = Bw + (ks * 8 + tg) * BSTR5 + wn * 32 + ni * 8 + g;
                unsigned b0 = bp[0], b1 = bp[4 * BSTR5];
#pragma unroll
                for (int mi = 0; mi < 4; mi++)
                    mma_f16(acc[mi][ni], a[mi], b0, b1);
            }
        }

        if (more) CP_WAIT0();
        __syncthreads();
    }

    // ---- epilogue ----
    if (wn * 32 >= ncols) return;
#pragma unroll
    for (int mi = 0; mi < 4; mi++) {
        int r = m0 + wm * 64 + mi * 16 + g;
#pragma unroll
        for (int ni = 0; ni < 4; ni++) {
            int cl = wn * 32 + ni * 8 + 2 * tg;
            float b0 = bias[cl], b1 = bias[cl + 1];
            float v0 = acc[mi][ni][0] + b0, v1 = acc[mi][ni][1] + b1;
            float v2 = acc[mi][ni][2] + b0, v3 = acc[mi][ni][3] + b1;
            if (RELU) {
                v0 = fmaxf(v0, 0.f); v1 = fmaxf(v1, 0.f);
                v2 = fmaxf(v2, 0.f); v3 = fmaxf(v3, 0.f);
            }
            if (OUTH) {
                unsigned* Ch = (unsigned*)Cp;
                int w = c0o + wn * 16 + ni * 4 + tg;
                Ch[(size_t)r * ldCo + w]       = h2u(__floats2half2_rn(v0, v1));
                Ch[(size_t)(r + 8) * ldCo + w] = h2u(__floats2half2_rn(v2, v3));
            } else {
                float* Cf = (float*)Cp;
                *(float2*)(Cf + (size_t)r * ldCo + c0o + cl)       = make_float2(v0, v1);
                *(float2*)(Cf + (size_t)(r + 8) * ldCo + c0o + cl) = make_float2(v2, v3);
            }
        }
    }
}

__global__ __launch_bounds__(256, 2) void qkv_v6(
    const float* __restrict__ bq, const float* __restrict__ bk,
    const float* __restrict__ bv, const float* __restrict__ bi)
{
    extern __shared__ unsigned smw[];
    const int nt = blockIdx.x, m0 = blockIdx.y * 128;
    if (nt < 24) {
        const int seg = nt >> 3, tile = nt & 7;
        const __half2* W = (seg == 0) ? g_whq : (seg == 1) ? g_whk : g_whv;
        const float* bb  = (seg == 0) ? bq : (seg == 1) ? bk : bv;
        gemm_core6<true, false>(g_xh, 512, 1024, m0, W, 1024, tile * 128, 128,
                                bb + tile * 128, g_qkvh, 1536,
                                seg * 512 + tile * 64, smw);
    } else {
        gemm_core6<true, false>(g_xh, 512, 1024, m0, g_whi, 64, 0, 64,
                                bi, g_cath, 544, 512, smw);
    }
}

__global__ __launch_bounds__(256, 2) void ffn1_v6(const float* __restrict__ b1)
{
    extern __shared__ unsigned smw[];
    const int n0 = blockIdx.x * 128;
    gemm_core6<true, true>(g_cath, 544, 1088, blockIdx.y * 128, g_wh1, DFF, n0, 128,
                           b1 + n0, g_hh, 1024, n0 >> 1, smw);
}

__global__ __launch_bounds__(256, 2) void ffn2_v6(const float* __restrict__ b2,
                                                  float* __restrict__ out)
{
    extern __shared__ unsigned smw[];
    const int n0 = blockIdx.x * 128;
    gemm_core6<false, false>(g_hh, 1024, 2048, blockIdx.y * 128, g_wh2, DIM, n0, 128,
                             b2 + n0, out, DIM, n0, smw);
}

// ---------------------------------------------------------------------------
// fp16 flash attention: 256 thr / 8 warps, 128 q rows, 32-key chunks,
// Q fragments hoisted to registers.
// ---------------------------------------------------------------------------
#define AQSTR 36
#define AVSTR 20
#define APSTR 20

__global__ __launch_bounds__(256) void attn_f16()
{
    __shared__ unsigned Qs[128 * AQSTR];
    __shared__ unsigned Ks[32 * AQSTR];
    __shared__ unsigned Vt[64 * AVSTR];
    __shared__ unsigned Ps[8 * 16 * APSTR];

    const int tid = threadIdx.x, lane = tid & 31, warp = tid >> 5;
    const int g = lane >> 2, tg = lane & 3;
    const int b = blockIdx.z, h = blockIdx.y, q0 = blockIdx.x * 128;

    const unsigned* qbase = (const unsigned*)g_qkvh + (size_t)(b * SEQ) * 1536 + h * 32;
    const unsigned* kbase = qbase + 512;
    const unsigned* vbase = qbase + 1024;

    // Q tile 128 rows x 32 words, scaled by 0.125
    {
        const __half2 qsc = __float2half2_rn(0.125f);
#pragma unroll
        for (int i = 0; i < 4; i++) {
            int idx = i * 256 + tid;
            int row = idx >> 3, c4 = (idx & 7) << 2;
            uint4 v = *(const uint4*)(qbase + (size_t)(q0 + row) * 1536 + c4);
            __half2* hp = (__half2*)&v;
            hp[0] = __hmul2(hp[0], qsc); hp[1] = __hmul2(hp[1], qsc);
            hp[2] = __hmul2(hp[2], qsc); hp[3] = __hmul2(hp[3], qsc);
            *(uint4*)(Qs + row * AQSTR + c4) = v;
        }
    }
    __syncthreads();

    // Hoist Q fragments into registers (loop-invariant)
    unsigned aq[4][4];
#pragma unroll
    for (int ks = 0; ks < 4; ks++) {
        const unsigned* qp = Qs + (warp * 16 + g) * AQSTR + ks * 8 + tg;
        aq[ks][0] = qp[0];             aq[ks][2] = qp[4];
        aq[ks][1] = qp[8 * AQSTR];     aq[ks][3] = qp[8 * AQSTR + 4];
    }

    float rowm[2] = {-1e30f, -1e30f};
    float rowl[2] = {0.f, 0.f};
    float o[8][4];
#pragma unroll
    for (int nf = 0; nf < 8; nf++)
#pragma unroll
        for (int r = 0; r < 4; r++) o[nf][r] = 0.f;

    const int qrow0 = q0 + warp * 16 + g;
    unsigned* Pw = Ps + warp * 16 * APSTR;

    for (int c0 = 0; c0 < SEQ; c0 += 32) {
        __syncthreads();
        // K tile 32 rows x 32 words
        {
            int row = tid >> 3, c4 = (tid & 7) << 2;
            *(uint4*)(Ks + row * AQSTR + c4) =
                *(const uint4*)(kbase + (size_t)(c0 + row) * 1536 + c4);
        }
        // V transpose to Vt[d][kp]
        {
            int wi = tid & 31, rb = tid >> 5;
#pragma unroll
            for (int rr = rb; rr < 16; rr += 8) {
                unsigned u0 = vbase[(size_t)(c0 + 2 * rr) * 1536 + wi];
                unsigned u1 = vbase[(size_t)(c0 + 2 * rr + 1) * 1536 + wi];
                __half2 va = u2h(u0), vb = u2h(u1);
                Vt[(2 * wi) * AVSTR + rr]     = h2u(__lows2half2(va, vb));
                Vt[(2 * wi + 1) * AVSTR + rr] = h2u(__highs2half2(va, vb));
            }
        }
        __syncthreads();

        // S = Q · K^T
        float s[4][4];
#pragma unroll
        for (int ni = 0; ni < 4; ni++)
#pragma unroll
            for (int r = 0; r < 4; r++) s[ni][r] = 0.f;
#pragma unroll
        for (int ks = 0; ks < 4; ks++) {
#pragma unroll
            for (int ni = 0; ni < 4; ni++) {
                const unsigned* kp = Ks + (ni * 8 + g) * AQSTR + ks * 8 + tg;
                mma_f16(s[ni], aq[ks], kp[0], kp[4]);
            }
        }

        // Diagonal mask + online softmax
        float cm0 = -1e30f, cm1 = -1e30f;
#pragma unroll
        for (int ni = 0; ni < 4; ni++) {
            int col = c0 + ni * 8 + 2 * tg;
            if (col     == qrow0)     s[ni][0] = -1e30f;
            if (col + 1 == qrow0)     s[ni][1] = -1e30f;
            if (col     == qrow0 + 8) s[ni][2] = -1e30f;
            if (col + 1 == qrow0 + 8) s[ni][3] = -1e30f;
            cm0 = fmaxf(cm0, fmaxf(s[ni][0], s[ni][1]));
            cm1 = fmaxf(cm1, fmaxf(s[ni][2], s[ni][3]));
        }
        cm0 = fmaxf(cm0, __shfl_xor_sync(0xffffffffu, cm0, 1));
        cm0 = fmaxf(cm0, __shfl_xor_sync(0xffffffffu, cm0, 2));
        cm1 = fmaxf(cm1, __shfl_xor_sync(0xffffffffu, cm1, 1));
        cm1 = fmaxf(cm1, __shfl_xor_sync(0xffffffffu, cm1, 2));

        float mn0 = fmaxf(rowm[0], cm0), mn1 = fmaxf(rowm[1], cm1);
        float sc0 = __expf(rowm[0] - mn0), sc1 = __expf(rowm[1] - mn1);
        rowm[0] = mn0; rowm[1] = mn1;
        rowl[0] *= sc0; rowl[1] *= sc1;
#pragma unroll
        for (int nf = 0; nf < 8; nf++) {
            o[nf][0] *= sc0; o[nf][1] *= sc0;
            o[nf][2] *= sc1; o[nf][3] *= sc1;
        }

        float ls0 = 0.f, ls1 = 0.f;
#pragma unroll
        for (int ni = 0; ni < 4; ni++) {
            float p0 = __expf(s[ni][0] - mn0), p1 = __expf(s[ni][1] - mn0);
            float p2 = __expf(s[ni][2] - mn1), p3 = __expf(s[ni][3] - mn1);
            ls0 += p0 + p1; ls1 += p2 + p3;
            Pw[g * APSTR + ni * 4 + tg]       = h2u(__floats2half2_rn(p0, p1));
            Pw[(g + 8) * APSTR + ni * 4 + tg] = h2u(__floats2half2_rn(p2, p3));
        }
        ls0 += __shfl_xor_sync(0xffffffffu, ls0, 1);
        ls0 += __shfl_xor_sync(0xffffffffu, ls0, 2);
        ls1 += __shfl_xor_sync(0xffffffffu, ls1, 1);
        ls1 += __shfl_xor_sync(0xffffffffu, ls1, 2);
        rowl[0] += ls0; rowl[1] += ls1;
        __syncwarp();

        // O += P · V
#pragma unroll
        for (int ks = 0; ks < 2; ks++) {
            unsigned a[4];
            a[0] = Pw[g * APSTR + ks * 8 + tg];
            a[1] = Pw[(g + 8) * APSTR + ks * 8 + tg];
            a[2] = Pw[g * APSTR + ks * 8 + tg + 4];
            a[3] = Pw[(g + 8) * APSTR + ks * 8 + tg + 4];
#pragma unroll
            for (int nf = 0; nf < 8; nf++) {
                const unsigned* vp = Vt + (nf * 8 + g) * AVSTR + ks * 8 + tg;
                mma_f16(o[nf], a, vp[0], vp[4]);
            }
        }
    }

    // Epilogue
    float inv0 = 1.f / rowl[0], inv1 = 1.f / rowl[1];
    unsigned* orow = (unsigned*)g_cath + (size_t)(b * SEQ + qrow0) * 544 + h * 32;
#pragma unroll
    for (int nf = 0; nf < 8; nf++) {
        int w = nf * 4 + tg;
        orow[w]           = h2u(__floats2half2_rn(o[nf][0] * inv0, o[nf][1] * inv0));
        orow[8 * 544 + w] = h2u(__floats2half2_rn(o[nf][2] * inv1, o[nf][3] * inv1));
    }
}

// ---------------------------------------------------------------------------
extern "C" void kernel_launch(void* const* d_in, const int* in_sizes, int n_in,
                              void* d_out, int out_size)
{
    const float* x   = (const float*)d_in[0];
    const float* Wq  = (const float*)d_in[1];
    const float* bq  = (const float*)d_in[2];
    const float* Wk  = (const float*)d_in[3];
    const float* bk  = (const float*)d_in[4];
    const float* Wv  = (const float*)d_in[5];
    const float* bv  = (const float*)d_in[6];
    const float* Wi  = (const float*)d_in[7];
    const float* bi  = (const float*)d_in[8];
    const float* W1  = (const float*)d_in[9];
    const float* b1  = (const float*)d_in[10];
    const float* W2  = (const float*)d_in[11];
    const float* b2  = (const float*)d_in[12];
    float* out = (float*)d_out;

    static bool configured = false;
    if (!configured) {
        cudaFuncSetAttribute(qkv_v6,  cudaFuncAttributeMaxDynamicSharedMemorySize, SMEM5);
        cudaFuncSetAttribute(ffn1_v6, cudaFuncAttributeMaxDynamicSharedMemorySize, SMEM5);
        cudaFuncSetAttribute(ffn2_v6, cudaFuncAttributeMaxDynamicSharedMemorySize, SMEM5);
        configured = true;
    }

    // 1: all conversions
    conv_all<<<(TTOT + 255) / 256, 256>>>(x, Wq, Wk, Wv, Wi, W1, W2);
    // 2: QKV + input projection
    qkv_v6<<<dim3(25, 64), 256, SMEM5>>>(bq, bk, bv, bi);
    // 3: Attention -> g_cath[:, 0:512w]
    attn_f16<<<dim3(SEQ / 128, NH, BSZ), 256>>>();
    // 4: FFN1 -> g_hh (relu)
    ffn1_v6<<<dim3(DFF / 128, MTOT / 128), 256, SMEM5>>>(b1);
    // 5: FFN2 -> out (fp32)   [ncu capture target]
    ffn2_v6<<<dim3(DIM / 128, MTOT / 128), 256, SMEM5>>>(b2, out);
}

// round 15
// speedup vs baseline: 1.5167x; 1.0414x over previous
#include <cuda_runtime.h>
#include <cuda_fp16.h>
#include <math.h>
#include <stdint.h>

#define BSZ 8
#define SEQ 1024
#define DIM 1024
#define NH 16
#define HD 64
#define MTOT 8192
#define DCAT 1088
#define DFF 2048

// fp16 intermediates (__device__ globals per allocation-free rule), half2 words
__device__ __half2 g_xh[(size_t)MTOT * 512];      // x            [m, 512w]
__device__ __half2 g_qkvh[(size_t)MTOT * 1536];   // q | k | v    [m, 1536w]
__device__ __half2 g_cath[(size_t)MTOT * 544];    // attn|inproj  [m, 544w]
__device__ __half2 g_hh[(size_t)MTOT * 1024];     // ffn hidden   [m, 1024w]

// Pre-converted weights: word(kp, n) = half2(W[2kp][n], W[2kp+1][n])
__device__ __half2 g_whq[512 * 1024];
__device__ __half2 g_whk[512 * 1024];
__device__ __half2 g_whv[512 * 1024];
__device__ __half2 g_whi[512 * 64];
__device__ __half2 g_wh1[544 * 2048];
__device__ __half2 g_wh2[1024 * 1024];

__device__ __forceinline__ unsigned h2u(__half2 h) { return *(unsigned*)&h; }
__device__ __forceinline__ __half2 u2h(unsigned u) { return *(__half2*)&u; }
__device__ __forceinline__ void mma_f16(float c[4], const unsigned a[4],
                                        unsigned b0, unsigned b1) {
    asm volatile(
        "mma.sync.aligned.m16n8k16.row.col.f32.f16.f16.f32 "
        "{%0,%1,%2,%3}, {%4,%5,%6,%7}, {%8,%9}, {%0,%1,%2,%3};"
        : "+f"(c[0]), "+f"(c[1]), "+f"(c[2]), "+f"(c[3])
        : "r"(a[0]), "r"(a[1]), "r"(a[2]), "r"(a[3]), "r"(b0), "r"(b1));
}
__device__ __forceinline__ void ldsm4(unsigned a[4], uint32_t addr) {
    asm volatile("ldmatrix.sync.aligned.m8n8.x4.shared.b16 {%0,%1,%2,%3}, [%4];"
        : "=r"(a[0]), "=r"(a[1]), "=r"(a[2]), "=r"(a[3]) : "r"(addr));
}
__device__ __forceinline__ uint32_t smem_u32(const void* p) {
    uint32_t a;
    asm("{ .reg .u64 t; cvta.to.shared.u64 t, %1; cvt.u32.u64 %0, t; }" : "=r"(a) : "l"(p));
    return a;
}
__device__ __forceinline__ void cp_async16(uint32_t dst, const void* src) {
    asm volatile("cp.async.cg.shared.global [%0], [%1], 16;" :: "r"(dst), "l"(src));
}
#define CP_COMMIT() asm volatile("cp.async.commit_group;" ::: "memory")
#define CP_WAIT0()  asm volatile("cp.async.wait_group 0;" ::: "memory")
#define CP_WAIT1()  asm volatile("cp.async.wait_group 1;" ::: "memory")

// ---------------------------------------------------------------------------
// Merged conversion kernel (one launch).
// ---------------------------------------------------------------------------
#define TX   (MTOT * 256)
#define TWQ  (512 * 256)
#define TWI  (512 * 16)
#define TW1  (544 * 512)
#define TW2  (1024 * 256)
#define TTOT (TX + 3 * TWQ + TWI + TW1 + TW2)

__device__ __forceinline__ void conv_w_task(
    const float* __restrict__ W, __half2* __restrict__ Wh, int N, int t)
{
    int nq = N >> 2;
    int kp = t / nq, n4 = (t - kp * nq) << 2;
    float4 a = *(const float4*)(W + (size_t)(2 * kp) * N + n4);
    float4 b = *(const float4*)(W + (size_t)(2 * kp + 1) * N + n4);
    uint4 o;
    o.x = h2u(__floats2half2_rn(a.x, b.x));
    o.y = h2u(__floats2half2_rn(a.y, b.y));
    o.z = h2u(__floats2half2_rn(a.z, b.z));
    o.w = h2u(__floats2half2_rn(a.w, b.w));
    *(uint4*)(Wh + (size_t)kp * N + n4) = o;
}

__global__ __launch_bounds__(256) void conv_all(
    const float* __restrict__ x,
    const float* __restrict__ Wq, const float* __restrict__ Wk,
    const float* __restrict__ Wv, const float* __restrict__ Wi,
    const float* __restrict__ W1, const float* __restrict__ W2)
{
    int idx = blockIdx.x * 256 + threadIdx.x;
    if (idx < TX) {
        int row = idx >> 8, c4 = (idx & 255) << 2;
        float4 v = *(const float4*)(x + (size_t)row * DIM + c4);
        uint2 o;
        o.x = h2u(__floats2half2_rn(v.x, v.y));
        o.y = h2u(__floats2half2_rn(v.z, v.w));
        *(uint2*)((unsigned*)g_xh + (size_t)row * 512 + (c4 >> 1)) = o;
        return;
    }
    idx -= TX;
    if (idx < TWQ) { conv_w_task(Wq, g_whq, 1024, idx); return; }
    idx -= TWQ;
    if (idx < TWQ) { conv_w_task(Wk, g_whk, 1024, idx); return; }
    idx -= TWQ;
    if (idx < TWQ) { conv_w_task(Wv, g_whv, 1024, idx); return; }
    idx -= TWQ;
    if (idx < TWI) { conv_w_task(Wi, g_whi, 64, idx); return; }
    idx -= TWI;
    if (idx < TW1) { conv_w_task(W1, g_wh1, 2048, idx); return; }
    idx -= TW1;
    if (idx < TW2) { conv_w_task(W2, g_wh2, 1024, idx); return; }
}

// ---------------------------------------------------------------------------
// fp16 GEMM v6 (proven): BK=64, ldmatrix A frags, CTA 128x128, 8 warps,
// 2-stage double buffer, 2 CTAs/SM.
// ---------------------------------------------------------------------------
#define ASTR5 36
#define BSTR5 136
#define A5W (128 * ASTR5)     // 4608
#define B5W (32 * BSTR5)      // 4352
#define STG5 (A5W + B5W)      // 8960 words
#define SMEM5 (2 * STG5 * 4)  // 71680 B

template<bool OUTH, bool RELU>
__device__ __forceinline__ void gemm_core6(
    const __half2* __restrict__ Ah, int ldaw, int K, int m0,
    const __half2* __restrict__ Bh, int ldw, int n0w, int ncols,
    const float* __restrict__ bias, void* Cp, int ldCo, int c0o,
    unsigned* smw)
{
    const int tid = threadIdx.x, lane = tid & 31, warp = tid >> 5;
    const int wm = warp & 1, wn = warp >> 1;
    const int g = lane >> 2, tg = lane & 3;
    const uint32_t ss = smem_u32(smw);

    const int lrow = lane & 7, sel = lane >> 3;
    const int arow_l = wm * 64 + ((sel & 1) << 3) + lrow;
    const int akoff_l = (sel >> 1) << 2;

    const int aoff[2] = {0, STG5};
    const int boff[2] = {A5W, STG5 + A5W};

    float acc[4][4][4];
#pragma unroll
    for (int mi = 0; mi < 4; mi++)
#pragma unroll
        for (int ni = 0; ni < 4; ni++)
#pragma unroll
            for (int r = 0; r < 4; r++) acc[mi][ni][r] = 0.f;

    const int NC = K >> 6;
    const int gpr = ncols >> 2;
    const int ngr = 32 * gpr;

#pragma unroll
    for (int i = 0; i < 4; i++) {
        int gi = i * 256 + tid;
        int row = gi >> 3, c4 = (gi & 7) << 2;
        cp_async16(ss + (aoff[0] + row * ASTR5 + c4) * 4,
                   Ah + (size_t)(m0 + row) * ldaw + c4);
    }
    for (int gi = tid; gi < ngr; gi += 256) {
        int row = gi / gpr, n4 = (gi - row * gpr) << 2;
        cp_async16(ss + (boff[0] + row * BSTR5 + n4) * 4,
                   Bh + (size_t)row * ldw + n0w + n4);
    }
    CP_COMMIT();
    CP_WAIT0();
    __syncthreads();

    for (int ch = 0; ch < NC; ch++) {
        const int s = ch & 1;
        const bool more = (ch + 1 < NC);
        if (more) {
            const int k0w = (ch + 1) << 5;
#pragma unroll
            for (int i = 0; i < 4; i++) {
                int gi = i * 256 + tid;
                int row = gi >> 3, c4 = (gi & 7) << 2;
                cp_async16(ss + (aoff[s ^ 1] + row * ASTR5 + c4) * 4,
                           Ah + (size_t)(m0 + row) * ldaw + k0w + c4);
            }
            for (int gi = tid; gi < ngr; gi += 256) {
                int row = gi / gpr, n4 = (gi - row * gpr) << 2;
                cp_async16(ss + (boff[s ^ 1] + row * BSTR5 + n4) * 4,
                           Bh + (size_t)(k0w + row) * ldw + n0w + n4);
            }
            CP_COMMIT();
        }

        const unsigned* Bw = smw + boff[s];
        const uint32_t abase = ss + (aoff[s] + arow_l * ASTR5 + akoff_l) * 4;
#pragma unroll
        for (int ks = 0; ks < 4; ks++) {
            unsigned a[4][4];
#pragma unroll
            for (int mi = 0; mi < 4; mi++)
                ldsm4(a[mi], abase + (mi * 16 * ASTR5 + ks * 8) * 4);
#pragma unroll
            for (int ni = 0; ni < 4; ni++) {
                const unsigned* bp = Bw + (ks * 8 + tg) * BSTR5 + wn * 32 + ni * 8 + g;
                unsigned b0 = bp[0], b1 = bp[4 * BSTR5];
#pragma unroll
                for (int mi = 0; mi < 4; mi++)
                    mma_f16(acc[mi][ni], a[mi], b0, b1);
            }
        }

        if (more) CP_WAIT0();
        __syncthreads();
    }

    if (wn * 32 >= ncols) return;
#pragma unroll
    for (int mi = 0; mi < 4; mi++) {
        int r = m0 + wm * 64 + mi * 16 + g;
#pragma unroll
        for (int ni = 0; ni < 4; ni++) {
            int cl = wn * 32 + ni * 8 + 2 * tg;
            float b0 = bias[cl], b1 = bias[cl + 1];
            float v0 = acc[mi][ni][0] + b0, v1 = acc[mi][ni][1] + b1;
            float v2 = acc[mi][ni][2] + b0, v3 = acc[mi][ni][3] + b1;
            if (RELU) {
                v0 = fmaxf(v0, 0.f); v1 = fmaxf(v1, 0.f);
                v2 = fmaxf(v2, 0.f); v3 = fmaxf(v3, 0.f);
            }
            if (OUTH) {
                unsigned* Ch = (unsigned*)Cp;
                int w = c0o + wn * 16 + ni * 4 + tg;
                Ch[(size_t)r * ldCo + w]       = h2u(__floats2half2_rn(v0, v1));
                Ch[(size_t)(r + 8) * ldCo + w] = h2u(__floats2half2_rn(v2, v3));
            } else {
                float* Cf = (float*)Cp;
                *(float2*)(Cf + (size_t)r * ldCo + c0o + cl)       = make_float2(v0, v1);
                *(float2*)(Cf + (size_t)(r + 8) * ldCo + c0o + cl) = make_float2(v2, v3);
            }
        }
    }
}

__global__ __launch_bounds__(256, 2) void qkv_v6(
    const float* __restrict__ bq, const float* __restrict__ bk,
    const float* __restrict__ bv, const float* __restrict__ bi)
{
    extern __shared__ unsigned smw[];
    const int nt = blockIdx.x, m0 = blockIdx.y * 128;
    if (nt < 24) {
        const int seg = nt >> 3, tile = nt & 7;
        const __half2* W = (seg == 0) ? g_whq : (seg == 1) ? g_whk : g_whv;
        const float* bb  = (seg == 0) ? bq : (seg == 1) ? bk : bv;
        gemm_core6<true, false>(g_xh, 512, 1024, m0, W, 1024, tile * 128, 128,
                                bb + tile * 128, g_qkvh, 1536,
                                seg * 512 + tile * 64, smw);
    } else {
        gemm_core6<true, false>(g_xh, 512, 1024, m0, g_whi, 64, 0, 64,
                                bi, g_cath, 544, 512, smw);
    }
}

__global__ __launch_bounds__(256, 2) void ffn1_v6(const float* __restrict__ b1)
{
    extern __shared__ unsigned smw[];
    const int n0 = blockIdx.x * 128;
    gemm_core6<true, true>(g_cath, 544, 1088, blockIdx.y * 128, g_wh1, DFF, n0, 128,
                           b1 + n0, g_hh, 1024, n0 >> 1, smw);
}

__global__ __launch_bounds__(256, 2) void ffn2_v6(const float* __restrict__ b2,
                                                  float* __restrict__ out)
{
    extern __shared__ unsigned smw[];
    const int n0 = blockIdx.x * 128;
    gemm_core6<false, false>(g_hh, 1024, 2048, blockIdx.y * 128, g_wh2, DIM, n0, 128,
                             b2 + n0, out, DIM, n0, smw);
}

// ---------------------------------------------------------------------------
// fp16 flash attention v4: 256 thr / 8 warps, 128 q rows, 32-key chunks.
// K and raw-V double-buffered via cp.async (prefetch next chunk during compute);
// V transpose reads staged smem. Q frags NOT hoisted (register/occupancy cliff).
// Dynamic smem layout (words):
//   Qs   [128*36] @ 0
//   Ks   [2][32*36] @ 4608
//   Vr   [2][32*36] @ 6912   (raw V rows)
//   Vt   [64*20]   @ 9216    (transposed, rebuilt per chunk)
//   Ps   [8*16*20] @ 10496
// total 13056 words = 52224 B
// ---------------------------------------------------------------------------
#define AQSTR 36
#define AVSTR 20
#define APSTR 20
#define AOQ   0
#define AOK(s)  (4608 + (s) * 1152)
#define AOVR(s) (6912 + (s) * 1152)
#define AOVT  9216
#define AOPS  10496
#define ASMEM (13056 * 4)

__global__ __launch_bounds__(256) void attn_f16()
{
    extern __shared__ unsigned smw[];
    const uint32_t ss = smem_u32(smw);

    const int tid = threadIdx.x, lane = tid & 31, warp = tid >> 5;
    const int g = lane >> 2, tg = lane & 3;
    const int b = blockIdx.z, h = blockIdx.y, q0 = blockIdx.x * 128;

    const unsigned* qbase = (const unsigned*)g_qkvh + (size_t)(b * SEQ) * 1536 + h * 32;
    const unsigned* kbase = qbase + 512;
    const unsigned* vbase = qbase + 1024;

    // Q tile 128 rows x 32 words, scaled by 0.125
    {
        const __half2 qsc = __float2half2_rn(0.125f);
#pragma unroll
        for (int i = 0; i < 4; i++) {
            int idx = i * 256 + tid;
            int row = idx >> 3, c4 = (idx & 7) << 2;
            uint4 v = *(const uint4*)(qbase + (size_t)(q0 + row) * 1536 + c4);
            __half2* hp = (__half2*)&v;
            hp[0] = __hmul2(hp[0], qsc); hp[1] = __hmul2(hp[1], qsc);
            hp[2] = __hmul2(hp[2], qsc); hp[3] = __hmul2(hp[3], qsc);
            *(uint4*)(smw + AOQ + row * AQSTR + c4) = v;
        }
    }

    // per-thread load geometry for K/Vr tiles (32 rows x 32 words; 1 uint4 each)
    const int lkrow = tid >> 3, lkc4 = (tid & 7) << 2;

    // prologue: chunk 0 K + Vraw
    cp_async16(ss + (AOK(0) + lkrow * AQSTR + lkc4) * 4,
               kbase + (size_t)lkrow * 1536 + lkc4);
    cp_async16(ss + (AOVR(0) + lkrow * AQSTR + lkc4) * 4,
               vbase + (size_t)lkrow * 1536 + lkc4);
    CP_COMMIT();
    CP_WAIT0();
    __syncthreads();

    float rowm[2] = {-1e30f, -1e30f};
    float rowl[2] = {0.f, 0.f};
    float o[8][4];
#pragma unroll
    for (int nf = 0; nf < 8; nf++)
#pragma unroll
        for (int r = 0; r < 4; r++) o[nf][r] = 0.f;

    const int qrow0 = q0 + warp * 16 + g;
    unsigned* Pw = smw + AOPS + warp * 16 * APSTR;
    const int twi = tid & 31, trb = tid >> 5;   // V transpose geometry

    for (int c0 = 0; c0 < SEQ; c0 += 32) {
        const int s = (c0 >> 5) & 1;
        const bool more = (c0 + 32 < SEQ);

        // prefetch next chunk into slot s^1
        if (more) {
            cp_async16(ss + (AOK(s ^ 1) + lkrow * AQSTR + lkc4) * 4,
                       kbase + (size_t)(c0 + 32 + lkrow) * 1536 + lkc4);
            cp_async16(ss + (AOVR(s ^ 1) + lkrow * AQSTR + lkc4) * 4,
                       vbase + (size_t)(c0 + 32 + lkrow) * 1536 + lkc4);
            CP_COMMIT();
        }

        // transpose staged Vr[s] -> Vt  (smem reads, conflict-free)
        {
            const unsigned* Vr = smw + AOVR(s);
            unsigned* Vt = smw + AOVT;
#pragma unroll
            for (int rr = trb; rr < 16; rr += 8) {
                unsigned u0 = Vr[(2 * rr) * AQSTR + twi];
                unsigned u1 = Vr[(2 * rr + 1) * AQSTR + twi];
                __half2 va = u2h(u0), vb = u2h(u1);
                Vt[(2 * twi) * AVSTR + rr]     = h2u(__lows2half2(va, vb));
                Vt[(2 * twi + 1) * AVSTR + rr] = h2u(__highs2half2(va, vb));
            }
        }

        // S = Q · K^T  (Ks[s] ready from prior wait+sync)
        const unsigned* Ks = smw + AOK(s);
        const unsigned* Qs = smw + AOQ;
        float sreg[4][4];
#pragma unroll
        for (int ni = 0; ni < 4; ni++)
#pragma unroll
            for (int r = 0; r < 4; r++) sreg[ni][r] = 0.f;
#pragma unroll
        for (int ks = 0; ks < 4; ks++) {
            unsigned a[4];
            const unsigned* qp = Qs + (warp * 16 + g) * AQSTR + ks * 8 + tg;
            a[0] = qp[0];             a[2] = qp[4];
            a[1] = qp[8 * AQSTR];     a[3] = qp[8 * AQSTR + 4];
#pragma unroll
            for (int ni = 0; ni < 4; ni++) {
                const unsigned* kp = Ks + (ni * 8 + g) * AQSTR + ks * 8 + tg;
                mma_f16(sreg[ni], a, kp[0], kp[4]);
            }
        }

        // Diagonal mask + online softmax
        float cm0 = -1e30f, cm1 = -1e30f;
#pragma unroll
        for (int ni = 0; ni < 4; ni++) {
            int col = c0 + ni * 8 + 2 * tg;
            if (col     == qrow0)     sreg[ni][0] = -1e30f;
            if (col + 1 == qrow0)     sreg[ni][1] = -1e30f;
            if (col     == qrow0 + 8) sreg[ni][2] = -1e30f;
            if (col + 1 == qrow0 + 8) sreg[ni][3] = -1e30f;
            cm0 = fmaxf(cm0, fmaxf(sreg[ni][0], sreg[ni][1]));
            cm1 = fmaxf(cm1, fmaxf(sreg[ni][2], sreg[ni][3]));
        }
        cm0 = fmaxf(cm0, __shfl_xor_sync(0xffffffffu, cm0, 1));
        cm0 = fmaxf(cm0, __shfl_xor_sync(0xffffffffu, cm0, 2));
        cm1 = fmaxf(cm1, __shfl_xor_sync(0xffffffffu, cm1, 1));
        cm1 = fmaxf(cm1, __shfl_xor_sync(0xffffffffu, cm1, 2));

        float mn0 = fmaxf(rowm[0], cm0), mn1 = fmaxf(rowm[1], cm1);
        float sc0 = __expf(rowm[0] - mn0), sc1 = __expf(rowm[1] - mn1);
        rowm[0] = mn0; rowm[1] = mn1;
        rowl[0] *= sc0; rowl[1] *= sc1;
#pragma unroll
        for (int nf = 0; nf < 8; nf++) {
            o[nf][0] *= sc0; o[nf][1] *= sc0;
            o[nf][2] *= sc1; o[nf][3] *= sc1;
        }

        float ls0 = 0.f, ls1 = 0.f;
#pragma unroll
        for (int ni = 0; ni < 4; ni++) {
            float p0 = __expf(sreg[ni][0] - mn0), p1 = __expf(sreg[ni][1] - mn0);
            float p2 = __expf(sreg[ni][2] - mn1), p3 = __expf(sreg[ni][3] - mn1);
            ls0 += p0 + p1; ls1 += p2 + p3;
            Pw[g * APSTR + ni * 4 + tg]       = h2u(__floats2half2_rn(p0, p1));
            Pw[(g + 8) * APSTR + ni * 4 + tg] = h2u(__floats2half2_rn(p2, p3));
        }
        ls0 += __shfl_xor_sync(0xffffffffu, ls0, 1);
        ls0 += __shfl_xor_sync(0xffffffffu, ls0, 2);
        ls1 += __shfl_xor_sync(0xffffffffu, ls1, 1);
        ls1 += __shfl_xor_sync(0xffffffffu, ls1, 2);
        rowl[0] += ls0; rowl[1] += ls1;

        // Vt writes (all threads) must be visible before PV mma reads
        __syncthreads();

        // O += P · V
        const unsigned* Vt = smw + AOVT;
#pragma unroll
        for (int ks = 0; ks < 2; ks++) {
            unsigned a[4];
            a[0] = Pw[g * APSTR + ks * 8 + tg];
            a[1] = Pw[(g + 8) * APSTR + ks * 8 + tg];
            a[2] = Pw[g * APSTR + ks * 8 + tg + 4];
            a[3] = Pw[(g + 8) * APSTR + ks * 8 + tg + 4];
#pragma unroll
            for (int nf = 0; nf < 8; nf++) {
                const unsigned* vp = Vt + (nf * 8 + g) * AVSTR + ks * 8 + tg;
                mma_f16(o[nf], a, vp[0], vp[4]);
            }
        }

        // wait for prefetched chunk, then barrier: Vt free + next K/Vr visible
        if (more) CP_WAIT0();
        __syncthreads();
    }

    // Epilogue
    float inv0 = 1.f / rowl[0], inv1 = 1.f / rowl[1];
    unsigned* orow = (unsigned*)g_cath + (size_t)(b * SEQ + qrow0) * 544 + h * 32;
#pragma unroll
    for (int nf = 0; nf < 8; nf++) {
        int w = nf * 4 + tg;
        orow[w]           = h2u(__floats2half2_rn(o[nf][0] * inv0, o[nf][1] * inv0));
        orow[8 * 544 + w] = h2u(__floats2half2_rn(o[nf][2] * inv1, o[nf][3] * inv1));
    }
}

// ---------------------------------------------------------------------------
extern "C" void kernel_launch(void* const* d_in, const int* in_sizes, int n_in,
                              void* d_out, int out_size)
{
    const float* x   = (const float*)d_in[0];
    const float* Wq  = (const float*)d_in[1];
    const float* bq  = (const float*)d_in[2];
    const float* Wk  = (const float*)d_in[3];
    const float* bk  = (const float*)d_in[4];
    const float* Wv  = (const float*)d_in[5];
    const float* bv  = (const float*)d_in[6];
    const float* Wi  = (const float*)d_in[7];
    const float* bi  = (const float*)d_in[8];
    const float* W1  = (const float*)d_in[9];
    const float* b1  = (const float*)d_in[10];
    const float* W2  = (const float*)d_in[11];
    const float* b2  = (const float*)d_in[12];
    float* out = (float*)d_out;

    static bool configured = false;
    if (!configured) {
        cudaFuncSetAttribute(qkv_v6,   cudaFuncAttributeMaxDynamicSharedMemorySize, SMEM5);
        cudaFuncSetAttribute(ffn1_v6,  cudaFuncAttributeMaxDynamicSharedMemorySize, SMEM5);
        cudaFuncSetAttribute(ffn2_v6,  cudaFuncAttributeMaxDynamicSharedMemorySize, SMEM5);
        cudaFuncSetAttribute(attn_f16, cudaFuncAttributeMaxDynamicSharedMemorySize, ASMEM);
        configured = true;
    }

    // 1: all conversions
    conv_all<<<(TTOT + 255) / 256, 256>>>(x, Wq, Wk, Wv, Wi, W1, W2);
    // 2: QKV + input projection
    qkv_v6<<<dim3(25, 64), 256, SMEM5>>>(bq, bk, bv, bi);
    // 3: Attention -> g_cath[:, 0:512w]
    attn_f16<<<dim3(SEQ / 128, NH, BSZ), 256, ASMEM>>>();
    // 4: FFN1 -> g_hh (relu)
    ffn1_v6<<<dim3(DFF / 128, MTOT / 128), 256, SMEM5>>>(b1);
    // 5: FFN2 -> out (fp32)   [ncu capture target]
    ffn2_v6<<<dim3(DIM / 128, MTOT / 128), 256, SMEM5>>>(b2, out);
}

// round 16
// speedup vs baseline: 1.5217x; 1.0033x over previous
#include <cuda_runtime.h>
#include <cuda_fp16.h>
#include <math.h>
#include <stdint.h>

#define BSZ 8
#define SEQ 1024
#define DIM 1024
#define NH 16
#define HD 64
#define MTOT 8192
#define DCAT 1088
#define DFF 2048

// fp16 intermediates (__device__ globals per allocation-free rule), half2 words
__device__ __half2 g_xh[(size_t)MTOT * 512];      // x            [m, 512w]
__device__ __half2 g_qkvh[(size_t)MTOT * 1536];   // q | k | v    [m, 1536w]
__device__ __half2 g_cath[(size_t)MTOT * 544];    // attn|inproj  [m, 544w]
__device__ __half2 g_hh[(size_t)MTOT * 1024];     // ffn hidden   [m, 1024w]

// Pre-converted weights: word(kp, n) = half2(W[2kp][n], W[2kp+1][n])
__device__ __half2 g_whq[512 * 1024];
__device__ __half2 g_whk[512 * 1024];
__device__ __half2 g_whv[512 * 1024];
__device__ __half2 g_whi[512 * 64];
__device__ __half2 g_wh1[544 * 2048];
__device__ __half2 g_wh2[1024 * 1024];

__device__ __forceinline__ unsigned h2u(__half2 h) { return *(unsigned*)&h; }
__device__ __forceinline__ __half2 u2h(unsigned u) { return *(__half2*)&u; }
__device__ __forceinline__ void mma_f16(float c[4], const unsigned a[4],
                                        unsigned b0, unsigned b1) {
    asm volatile(
        "mma.sync.aligned.m16n8k16.row.col.f32.f16.f16.f32 "
        "{%0,%1,%2,%3}, {%4,%5,%6,%7}, {%8,%9}, {%0,%1,%2,%3};"
        : "+f"(c[0]), "+f"(c[1]), "+f"(c[2]), "+f"(c[3])
        : "r"(a[0]), "r"(a[1]), "r"(a[2]), "r"(a[3]), "r"(b0), "r"(b1));
}
__device__ __forceinline__ void ldsm4(unsigned a[4], uint32_t addr) {
    asm volatile("ldmatrix.sync.aligned.m8n8.x4.shared.b16 {%0,%1,%2,%3}, [%4];"
        : "=r"(a[0]), "=r"(a[1]), "=r"(a[2]), "=r"(a[3]) : "r"(addr));
}
__device__ __forceinline__ uint32_t smem_u32(const void* p) {
    uint32_t a;
    asm("{ .reg .u64 t; cvta.to.shared.u64 t, %1; cvt.u32.u64 %0, t; }" : "=r"(a) : "l"(p));
    return a;
}
__device__ __forceinline__ void cp_async16(uint32_t dst, const void* src) {
    asm volatile("cp.async.cg.shared.global [%0], [%1], 16;" :: "r"(dst), "l"(src));
}
#define CP_COMMIT() asm volatile("cp.async.commit_group;" ::: "memory")
#define CP_WAIT0()  asm volatile("cp.async.wait_group 0;" ::: "memory")

// ---------------------------------------------------------------------------
// Merged conversion kernel: 4 independent tasks per thread (MLP=4).
// ---------------------------------------------------------------------------
#define TX   (MTOT * 256)
#define TWQ  (512 * 256)
#define TWI  (512 * 16)
#define TW1  (544 * 512)
#define TW2  (1024 * 256)
#define TTOT (TX + 3 * TWQ + TWI + TW1 + TW2)

__device__ __forceinline__ void conv_w_task(
    const float* __restrict__ W, __half2* __restrict__ Wh, int N, int t)
{
    int nq = N >> 2;
    int kp = t / nq, n4 = (t - kp * nq) << 2;
    float4 a = *(const float4*)(W + (size_t)(2 * kp) * N + n4);
    float4 b = *(const float4*)(W + (size_t)(2 * kp + 1) * N + n4);
    uint4 o;
    o.x = h2u(__floats2half2_rn(a.x, b.x));
    o.y = h2u(__floats2half2_rn(a.y, b.y));
    o.z = h2u(__floats2half2_rn(a.z, b.z));
    o.w = h2u(__floats2half2_rn(a.w, b.w));
    *(uint4*)(Wh + (size_t)kp * N + n4) = o;
}

__device__ __forceinline__ void conv_task(
    int idx,
    const float* __restrict__ x,
    const float* __restrict__ Wq, const float* __restrict__ Wk,
    const float* __restrict__ Wv, const float* __restrict__ Wi,
    const float* __restrict__ W1, const float* __restrict__ W2)
{
    if (idx < TX) {
        int row = idx >> 8, c4 = (idx & 255) << 2;
        float4 v = *(const float4*)(x + (size_t)row * DIM + c4);
        uint2 o;
        o.x = h2u(__floats2half2_rn(v.x, v.y));
        o.y = h2u(__floats2half2_rn(v.z, v.w));
        *(uint2*)((unsigned*)g_xh + (size_t)row * 512 + (c4 >> 1)) = o;
        return;
    }
    idx -= TX;
    if (idx < TWQ) { conv_w_task(Wq, g_whq, 1024, idx); return; }
    idx -= TWQ;
    if (idx < TWQ) { conv_w_task(Wk, g_whk, 1024, idx); return; }
    idx -= TWQ;
    if (idx < TWQ) { conv_w_task(Wv, g_whv, 1024, idx); return; }
    idx -= TWQ;
    if (idx < TWI) { conv_w_task(Wi, g_whi, 64, idx); return; }
    idx -= TWI;
    if (idx < TW1) { conv_w_task(W1, g_wh1, 2048, idx); return; }
    idx -= TW1;
    if (idx < TW2) { conv_w_task(W2, g_wh2, 1024, idx); return; }
}

__global__ __launch_bounds__(256) void conv_all(
    const float* __restrict__ x,
    const float* __restrict__ Wq, const float* __restrict__ Wk,
    const float* __restrict__ Wv, const float* __restrict__ Wi,
    const float* __restrict__ W1, const float* __restrict__ W2)
{
    int base = blockIdx.x * 1024 + threadIdx.x;
#pragma unroll
    for (int i = 0; i < 4; i++) {
        int idx = base + i * 256;
        if (idx < TTOT) conv_task(idx, x, Wq, Wk, Wv, Wi, W1, W2);
    }
}

// ---------------------------------------------------------------------------
// fp16 GEMM v6 (proven): BK=64, ldmatrix A frags, CTA 128x128, 8 warps,
// 2-stage double buffer, 2 CTAs/SM.
// ---------------------------------------------------------------------------
#define ASTR5 36
#define BSTR5 136
#define A5W (128 * ASTR5)     // 4608
#define B5W (32 * BSTR5)      // 4352
#define STG5 (A5W + B5W)      // 8960 words
#define SMEM5 (2 * STG5 * 4)  // 71680 B

template<bool OUTH, bool RELU>
__device__ __forceinline__ void gemm_core6(
    const __half2* __restrict__ Ah, int ldaw, int K, int m0,
    const __half2* __restrict__ Bh, int ldw, int n0w, int ncols,
    const float* __restrict__ bias, void* Cp, int ldCo, int c0o,
    unsigned* smw)
{
    const int tid = threadIdx.x, lane = tid & 31, warp = tid >> 5;
    const int wm = warp & 1, wn = warp >> 1;
    const int g = lane >> 2, tg = lane & 3;
    const uint32_t ss = smem_u32(smw);

    const int lrow = lane & 7, sel = lane >> 3;
    const int arow_l = wm * 64 + ((sel & 1) << 3) + lrow;
    const int akoff_l = (sel >> 1) << 2;

    const int aoff[2] = {0, STG5};
    const int boff[2] = {A5W, STG5 + A5W};

    float acc[4][4][4];
#pragma unroll
    for (int mi = 0; mi < 4; mi++)
#pragma unroll
        for (int ni = 0; ni < 4; ni++)
#pragma unroll
            for (int r = 0; r < 4; r++) acc[mi][ni][r] = 0.f;

    const int NC = K >> 6;
    const int gpr = ncols >> 2;
    const int ngr = 32 * gpr;

#pragma unroll
    for (int i = 0; i < 4; i++) {
        int gi = i * 256 + tid;
        int row = gi >> 3, c4 = (gi & 7) << 2;
        cp_async16(ss + (aoff[0] + row * ASTR5 + c4) * 4,
                   Ah + (size_t)(m0 + row) * ldaw + c4);
    }
    for (int gi = tid; gi < ngr; gi += 256) {
        int row = gi / gpr, n4 = (gi - row * gpr) << 2;
        cp_async16(ss + (boff[0] + row * BSTR5 + n4) * 4,
                   Bh + (size_t)row * ldw + n0w + n4);
    }
    CP_COMMIT();
    CP_WAIT0();
    __syncthreads();

    for (int ch = 0; ch < NC; ch++) {
        const int s = ch & 1;
        const bool more = (ch + 1 < NC);
        if (more) {
            const int k0w = (ch + 1) << 5;
#pragma unroll
            for (int i = 0; i < 4; i++) {
                int gi = i * 256 + tid;
                int row = gi >> 3, c4 = (gi & 7) << 2;
                cp_async16(ss + (aoff[s ^ 1] + row * ASTR5 + c4) * 4,
                           Ah + (size_t)(m0 + row) * ldaw + k0w + c4);
            }
            for (int gi = tid; gi < ngr; gi += 256) {
                int row = gi / gpr, n4 = (gi - row * gpr) << 2;
                cp_async16(ss + (boff[s ^ 1] + row * BSTR5 + n4) * 4,
                           Bh + (size_t)(k0w + row) * ldw + n0w + n4);
            }
            CP_COMMIT();
        }

        const unsigned* Bw = smw + boff[s];
        const uint32_t abase = ss + (aoff[s] + arow_l * ASTR5 + akoff_l) * 4;
#pragma unroll
        for (int ks = 0; ks < 4; ks++) {
            unsigned a[4][4];
#pragma unroll
            for (int mi = 0; mi < 4; mi++)
                ldsm4(a[mi], abase + (mi * 16 * ASTR5 + ks * 8) * 4);
#pragma unroll
            for (int ni = 0; ni < 4; ni++) {
                const unsigned* bp = Bw + (ks * 8 + tg) * BSTR5 + wn * 32 + ni * 8 + g;
                unsigned b0 = bp[0], b1 = bp[4 * BSTR5];
#pragma unroll
                for (int mi = 0; mi < 4; mi++)
                    mma_f16(acc[mi][ni], a[mi], b0, b1);
            }
        }

        if (more) CP_WAIT0();
        __syncthreads();
    }

    if (wn * 32 >= ncols) return;
#pragma unroll
    for (int mi = 0; mi < 4; mi++) {
        int r = m0 + wm * 64 + mi * 16 + g;
#pragma unroll
        for (int ni = 0; ni < 4; ni++) {
            int cl = wn * 32 + ni * 8 + 2 * tg;
            float b0 = bias[cl], b1 = bias[cl + 1];
            float v0 = acc[mi][ni][0] + b0, v1 = acc[mi][ni][1] + b1;
            float v2 = acc[mi][ni][2] + b0, v3 = acc[mi][ni][3] + b1;
            if (RELU) {
                v0 = fmaxf(v0, 0.f); v1 = fmaxf(v1, 0.f);
                v2 = fmaxf(v2, 0.f); v3 = fmaxf(v3, 0.f);
            }
            if (OUTH) {
                unsigned* Ch = (unsigned*)Cp;
                int w = c0o + wn * 16 + ni * 4 + tg;
                Ch[(size_t)r * ldCo + w]       = h2u(__floats2half2_rn(v0, v1));
                Ch[(size_t)(r + 8) * ldCo + w] = h2u(__floats2half2_rn(v2, v3));
            } else {
                float* Cf = (float*)Cp;
                *(float2*)(Cf + (size_t)r * ldCo + c0o + cl)       = make_float2(v0, v1);
                *(float2*)(Cf + (size_t)(r + 8) * ldCo + c0o + cl) = make_float2(v2, v3);
            }
        }
    }
}

__global__ __launch_bounds__(256, 2) void qkv_v6(
    const float* __restrict__ bq, const float* __restrict__ bk,
    const float* __restrict__ bv, const float* __restrict__ bi)
{
    extern __shared__ unsigned smw[];
    const int nt = blockIdx.x, m0 = blockIdx.y * 128;
    if (nt < 24) {
        const int seg = nt >> 3, tile = nt & 7;
        const __half2* W = (seg == 0) ? g_whq : (seg == 1) ? g_whk : g_whv;
        const float* bb  = (seg == 0) ? bq : (seg == 1) ? bk : bv;
        gemm_core6<true, false>(g_xh, 512, 1024, m0, W, 1024, tile * 128, 128,
                                bb + tile * 128, g_qkvh, 1536,
                                seg * 512 + tile * 64, smw);
    } else {
        gemm_core6<true, false>(g_xh, 512, 1024, m0, g_whi, 64, 0, 64,
                                bi, g_cath, 544, 512, smw);
    }
}

__global__ __launch_bounds__(256, 2) void ffn1_v6(const float* __restrict__ b1)
{
    extern __shared__ unsigned smw[];
    const int n0 = blockIdx.x * 128;
    gemm_core6<true, true>(g_cath, 544, 1088, blockIdx.y * 128, g_wh1, DFF, n0, 128,
                           b1 + n0, g_hh, 1024, n0 >> 1, smw);
}

__global__ __launch_bounds__(256, 2) void ffn2_v6(const float* __restrict__ b2,
                                                  float* __restrict__ out)
{
    extern __shared__ unsigned smw[];
    const int n0 = blockIdx.x * 128;
    gemm_core6<false, false>(g_hh, 1024, 2048, blockIdx.y * 128, g_wh2, DIM, n0, 128,
                             b2 + n0, out, DIM, n0, smw);
}

// ---------------------------------------------------------------------------
// fp16 flash attention v5: 256 thr / 8 warps, 128 q rows, 32-key chunks.
// K/Vr double-buffered via cp.async; Vt double-buffered -> ONE syncthreads
// per chunk. Dynamic smem (words):
//   Qs [128*36] @0 | Ks[2][32*36] @4608 | Vr[2][32*36] @6912
//   Vt[2][64*20] @9216 | Ps [8*16*20] @11776   -> 14336 w = 57344 B
// ---------------------------------------------------------------------------
#define AQSTR 36
#define AVSTR 20
#define APSTR 20
#define AOQ     0
#define AOK(s)  (4608 + (s) * 1152)
#define AOVR(s) (6912 + (s) * 1152)
#define AOVT(s) (9216 + (s) * 1280)
#define AOPS    11776
#define ASMEM   (14336 * 4)

__global__ __launch_bounds__(256) void attn_f16()
{
    extern __shared__ unsigned smw[];
    const uint32_t ss = smem_u32(smw);

    const int tid = threadIdx.x, lane = tid & 31, warp = tid >> 5;
    const int g = lane >> 2, tg = lane & 3;
    const int b = blockIdx.z, h = blockIdx.y, q0 = blockIdx.x * 128;

    const unsigned* qbase = (const unsigned*)g_qkvh + (size_t)(b * SEQ) * 1536 + h * 32;
    const unsigned* kbase = qbase + 512;
    const unsigned* vbase = qbase + 1024;

    // Q tile 128 rows x 32 words, scaled by 0.125
    {
        const __half2 qsc = __float2half2_rn(0.125f);
#pragma unroll
        for (int i = 0; i < 4; i++) {
            int idx = i * 256 + tid;
            int row = idx >> 3, c4 = (idx & 7) << 2;
            uint4 v = *(const uint4*)(qbase + (size_t)(q0 + row) * 1536 + c4);
            __half2* hp = (__half2*)&v;
            hp[0] = __hmul2(hp[0], qsc); hp[1] = __hmul2(hp[1], qsc);
            hp[2] = __hmul2(hp[2], qsc); hp[3] = __hmul2(hp[3], qsc);
            *(uint4*)(smw + AOQ + row * AQSTR + c4) = v;
        }
    }

    const int lkrow = tid >> 3, lkc4 = (tid & 7) << 2;

    // prologue: chunk 0 K + Vraw
    cp_async16(ss + (AOK(0) + lkrow * AQSTR + lkc4) * 4,
               kbase + (size_t)lkrow * 1536 + lkc4);
    cp_async16(ss + (AOVR(0) + lkrow * AQSTR + lkc4) * 4,
               vbase + (size_t)lkrow * 1536 + lkc4);
    CP_COMMIT();
    CP_WAIT0();
    __syncthreads();

    float rowm[2] = {-1e30f, -1e30f};
    float rowl[2] = {0.f, 0.f};
    float o[8][4];
#pragma unroll
    for (int nf = 0; nf < 8; nf++)
#pragma unroll
        for (int r = 0; r < 4; r++) o[nf][r] = 0.f;

    const int qrow0 = q0 + warp * 16 + g;
    unsigned* Pw = smw + AOPS + warp * 16 * APSTR;
    const int twi = tid & 31, trb = tid >> 5;

    for (int c0 = 0; c0 < SEQ; c0 += 32) {
        const int s = (c0 >> 5) & 1;
        const bool more = (c0 + 32 < SEQ);

        // prefetch next chunk into slot s^1
        if (more) {
            cp_async16(ss + (AOK(s ^ 1) + lkrow * AQSTR + lkc4) * 4,
                       kbase + (size_t)(c0 + 32 + lkrow) * 1536 + lkc4);
            cp_async16(ss + (AOVR(s ^ 1) + lkrow * AQSTR + lkc4) * 4,
                       vbase + (size_t)(c0 + 32 + lkrow) * 1536 + lkc4);
            CP_COMMIT();
        }

        // transpose staged Vr[s] -> Vt[s]
        {
            const unsigned* Vr = smw + AOVR(s);
            unsigned* Vt = smw + AOVT(s);
#pragma unroll
            for (int rr = trb; rr < 16; rr += 8) {
                unsigned u0 = Vr[(2 * rr) * AQSTR + twi];
                unsigned u1 = Vr[(2 * rr + 1) * AQSTR + twi];
                __half2 va = u2h(u0), vb = u2h(u1);
                Vt[(2 * twi) * AVSTR + rr]     = h2u(__lows2half2(va, vb));
                Vt[(2 * twi + 1) * AVSTR + rr] = h2u(__highs2half2(va, vb));
            }
        }

        // S = Q · K^T
        const unsigned* Ks = smw + AOK(s);
        const unsigned* Qs = smw + AOQ;
        float sreg[4][4];
#pragma unroll
        for (int ni = 0; ni < 4; ni++)
#pragma unroll
            for (int r = 0; r < 4; r++) sreg[ni][r] = 0.f;
#pragma unroll
        for (int ks = 0; ks < 4; ks++) {
            unsigned a[4];
            const unsigned* qp = Qs + (warp * 16 + g) * AQSTR + ks * 8 + tg;
            a[0] = qp[0];             a[2] = qp[4];
            a[1] = qp[8 * AQSTR];     a[3] = qp[8 * AQSTR + 4];
#pragma unroll
            for (int ni = 0; ni < 4; ni++) {
                const unsigned* kp = Ks + (ni * 8 + g) * AQSTR + ks * 8 + tg;
                mma_f16(sreg[ni], a, kp[0], kp[4]);
            }
        }

        // Diagonal mask + online softmax
        float cm0 = -1e30f, cm1 = -1e30f;
#pragma unroll
        for (int ni = 0; ni < 4; ni++) {
            int col = c0 + ni * 8 + 2 * tg;
            if (col     == qrow0)     sreg[ni][0] = -1e30f;
            if (col + 1 == qrow0)     sreg[ni][1] = -1e30f;
            if (col     == qrow0 + 8) sreg[ni][2] = -1e30f;
            if (col + 1 == qrow0 + 8) sreg[ni][3] = -1e30f;
            cm0 = fmaxf(cm0, fmaxf(sreg[ni][0], sreg[ni][1]));
            cm1 = fmaxf(cm1, fmaxf(sreg[ni][2], sreg[ni][3]));
        }
        cm0 = fmaxf(cm0, __shfl_xor_sync(0xffffffffu, cm0, 1));
        cm0 = fmaxf(cm0, __shfl_xor_sync(0xffffffffu, cm0, 2));
        cm1 = fmaxf(cm1, __shfl_xor_sync(0xffffffffu, cm1, 1));
        cm1 = fmaxf(cm1, __shfl_xor_sync(0xffffffffu, cm1, 2));

        float mn0 = fmaxf(rowm[0], cm0), mn1 = fmaxf(rowm[1], cm1);
        float sc0 = __expf(rowm[0] - mn0), sc1 = __expf(rowm[1] - mn1);
        rowm[0] = mn0; rowm[1] = mn1;
        rowl[0] *= sc0; rowl[1] *= sc1;
#pragma unroll
        for (int nf = 0; nf < 8; nf++) {
            o[nf][0] *= sc0; o[nf][1] *= sc0;
            o[nf][2] *= sc1; o[nf][3] *= sc1;
        }

        float ls0 = 0.f, ls1 = 0.f;
#pragma unroll
        for (int ni = 0; ni < 4; ni++) {
            float p0 = __expf(sreg[ni][0] - mn0), p1 = __expf(sreg[ni][1] - mn0);
            float p2 = __expf(sreg[ni][2] - mn1), p3 = __expf(sreg[ni][3] - mn1);
            ls0 += p0 + p1; ls1 += p2 + p3;
            Pw[g * APSTR + ni * 4 + tg]       = h2u(__floats2half2_rn(p0, p1));
            Pw[(g + 8) * APSTR + ni * 4 + tg] = h2u(__floats2half2_rn(p2, p3));
        }
        ls0 += __shfl_xor_sync(0xffffffffu, ls0, 1);
        ls0 += __shfl_xor_sync(0xffffffffu, ls0, 2);
        ls1 += __shfl_xor_sync(0xffffffffu, ls1, 1);
        ls1 += __shfl_xor_sync(0xffffffffu, ls1, 2);
        rowl[0] += ls0; rowl[1] += ls1;

        // single barrier: Vt[s] visible, own prefetch complete -> all complete
        if (more) CP_WAIT0();
        __syncthreads();

        // O += P · V  (reads Vt[s]; next chunk writes Vt[s^1] — no WAR)
        const unsigned* Vt = smw + AOVT(s);
#pragma unroll
        for (int ks = 0; ks < 2; ks++) {
            unsigned a[4];
            a[0] = Pw[g * APSTR + ks * 8 + tg];
            a[1] = Pw[(g + 8) * APSTR + ks * 8 + tg];
            a[2] = Pw[g * APSTR + ks * 8 + tg + 4];
            a[3] = Pw[(g + 8) * APSTR + ks * 8 + tg + 4];
#pragma unroll
            for (int nf = 0; nf < 8; nf++) {
                const unsigned* vp = Vt + (nf * 8 + g) * AVSTR + ks * 8 + tg;
                mma_f16(o[nf], a, vp[0], vp[4]);
            }
        }
    }

    // Epilogue
    float inv0 = 1.f / rowl[0], inv1 = 1.f / rowl[1];
    unsigned* orow = (unsigned*)g_cath + (size_t)(b * SEQ + qrow0) * 544 + h * 32;
#pragma unroll
    for (int nf = 0; nf < 8; nf++) {
        int w = nf * 4 + tg;
        orow[w]           = h2u(__floats2half2_rn(o[nf][0] * inv0, o[nf][1] * inv0));
        orow[8 * 544 + w] = h2u(__floats2half2_rn(o[nf][2] * inv1, o[nf][3] * inv1));
    }
}

// ---------------------------------------------------------------------------
extern "C" void kernel_launch(void* const* d_in, const int* in_sizes, int n_in,
                              void* d_out, int out_size)
{
    const float* x   = (const float*)d_in[0];
    const float* Wq  = (const float*)d_in[1];
    const float* bq  = (const float*)d_in[2];
    const float* Wk  = (const float*)d_in[3];
    const float* bk  = (const float*)d_in[4];
    const float* Wv  = (const float*)d_in[5];
    const float* bv  = (const float*)d_in[6];
    const float* Wi  = (const float*)d_in[7];
    const float* bi  = (const float*)d_in[8];
    const float* W1  = (const float*)d_in[9];
    const float* b1  = (const float*)d_in[10];
    const float* W2  = (const float*)d_in[11];
    const float* b2  = (const float*)d_in[12];
    float* out = (float*)d_out;

    static bool configured = false;
    if (!configured) {
        cudaFuncSetAttribute(qkv_v6,   cudaFuncAttributeMaxDynamicSharedMemorySize, SMEM5);
        cudaFuncSetAttribute(ffn1_v6,  cudaFuncAttributeMaxDynamicSharedMemorySize, SMEM5);
        cudaFuncSetAttribute(ffn2_v6,  cudaFuncAttributeMaxDynamicSharedMemorySize, SMEM5);
        cudaFuncSetAttribute(attn_f16, cudaFuncAttributeMaxDynamicSharedMemorySize, ASMEM);
        configured = true;
    }

    // 1: all conversions (4 tasks/thread)
    conv_all<<<(TTOT + 1023) / 1024, 256>>>(x, Wq, Wk, Wv, Wi, W1, W2);
    // 2: QKV + input projection
    qkv_v6<<<dim3(25, 64), 256, SMEM5>>>(bq, bk, bv, bi);
    // 3: Attention -> g_cath[:, 0:512w]
    attn_f16<<<dim3(SEQ / 128, NH, BSZ), 256, ASMEM>>>();
    // 4: FFN1 -> g_hh (relu)
    ffn1_v6<<<dim3(DFF / 128, MTOT / 128), 256, SMEM5>>>(b1);
    // 5: FFN2 -> out (fp32)   [ncu capture target]
    ffn2_v6<<<dim3(DIM / 128, MTOT / 128), 256, SMEM5>>>(b2, out);
}